// round 17
// baseline (speedup 1.0000x reference)
#include <cuda_runtime.h>
#include <cstdint>

// Until operator: r[t] = max(min(1, psi[t]), min(phi[t], r[t+1])), r[T] = -inf.
// [B=1024, T=8192, C=2] fp32. (max,min)-semiring reverse scan, exact.
//
// Op f_t(r) = max(v_t, min(p_t, r)), v_t = min(1, psi[t]).
// Compose (f earlier in time): P = min(Pf,Pg); V = max(Vf, min(Pf,Vg)).
//
// R14: cp.async double-buffered pipeline. R11/R12/R13 all froze at kernel
// 34.2us / DRAM 62% / L1 62% across different shapes -> the shared L1TEX/MIO
// front-end (load wavefronts + 40 SHFL/warp-iter + RF traffic) is the choke,
// not HBM. cp.async.cg moves global->smem around L1/RF entirely and
// decouples load completion from the consuming warp. BLK=128, ITERS=16,
// 2-stage smem buffer, 10 blocks/SM pinned -> 40 warps/SM, single wave
// (1480 slots >= 1024 blocks). Conflict-free padded LDS; direct STG.

#define B_ROWS 1024
#define T_LEN  8192
#define BLK    128
#define ROW_F4 (T_LEN * 2 / 4)     // 4096 float4 per row
#define ITERS  16
#define SEG_F4 (ROW_F4 / ITERS)    // 256 float4 per segment
#define NW     (BLK / 32)          // 4 warps

// Padded smem index (float4 units): conflict-free for linear writes and
// stride-2 float4 reads (verified: 8-lane LDS.128 phases hit 32 distinct banks).
#define SPAD(i) ((i) + ((i) >> 3))
#define SSZ     (SPAD(SEG_F4 - 1) + 2)   // 288

__device__ __forceinline__ float finf()  { return __int_as_float(0x7f800000); }
__device__ __forceinline__ float fninf() { return __int_as_float(0xff800000); }

__device__ __forceinline__ void cpa16(uint32_t dst, const void* src) {
    asm volatile("cp.async.cg.shared.global [%0], [%1], 16;"
                 :: "r"(dst), "l"(src) : "memory");
}

__global__ void __launch_bounds__(BLK, 10)
until_kernel(const float4* __restrict__ phi,
             const float4* __restrict__ psi,
             float4* __restrict__ out)
{
    const int    row  = blockIdx.x;
    const size_t base = (size_t)row * ROW_F4;
    const int    tid  = threadIdx.x;
    const int    lane = tid & 31;
    const int    w    = tid >> 5;

    __shared__ float4 sp[2][SSZ];   // staged phi, double-buffered
    __shared__ float4 sq[2][SSZ];   // staged psi, double-buffered
    __shared__ float4 wop[NW];      // per-warp composed op (Px,Vx,Py,Vy)

    // Per-thread smem dst addresses (coalesced stage layout).
    uint32_t dp0[2], dp1[2], dq0[2], dq1[2];
#pragma unroll
    for (int b = 0; b < 2; b++) {
        dp0[b] = (uint32_t)__cvta_generic_to_shared(&sp[b][SPAD(tid)]);
        dp1[b] = (uint32_t)__cvta_generic_to_shared(&sp[b][SPAD(BLK + tid)]);
        dq0[b] = (uint32_t)__cvta_generic_to_shared(&sq[b][SPAD(tid)]);
        dq1[b] = (uint32_t)__cvta_generic_to_shared(&sq[b][SPAD(BLK + tid)]);
    }

    // Prologue: async-issue the two latest-time segments.
    {
        const size_t s0 = base + (size_t)(ITERS - 1) * SEG_F4;
        cpa16(dp0[0], phi + s0 + tid);
        cpa16(dp1[0], phi + s0 + BLK + tid);
        cpa16(dq0[0], psi + s0 + tid);
        cpa16(dq1[0], psi + s0 + BLK + tid);
        asm volatile("cp.async.commit_group;" ::: "memory");
        const size_t s1 = base + (size_t)(ITERS - 2) * SEG_F4;
        cpa16(dp0[1], phi + s1 + tid);
        cpa16(dp1[1], phi + s1 + BLK + tid);
        cpa16(dq0[1], psi + s1 + tid);
        cpa16(dq1[1], psi + s1 + BLK + tid);
        asm volatile("cp.async.commit_group;" ::: "memory");
    }

    float cx = fninf(), cy = fninf();   // inter-iteration carry (identical copy
                                        // in every warp — redundant resolve)
    const int e0 = 2 * tid, e1 = 2 * tid + 1;

#pragma unroll 1
    for (int i = ITERS - 1; i >= 0; --i) {
        const int buf = (ITERS - 1 - i) & 1;

        // Wait for this segment's group (all but the most recent; at i==0
        // nothing newer is outstanding, so drain fully).
        if (i == 0) asm volatile("cp.async.wait_group 0;" ::: "memory");
        else        asm volatile("cp.async.wait_group 1;" ::: "memory");
        __syncthreads();   // B1: everyone's data visible

        // Consume: 2 time-contiguous float4s = timesteps 4t..4t+3.
        float4 p0 = sp[buf][SPAD(e0)];
        float4 p1 = sp[buf][SPAD(e1)];
        float4 q0 = sq[buf][SPAD(e0)];
        float4 q1 = sq[buf][SPAD(e1)];

        // v = min(1, psi). Layout: .x=ch0@t, .y=ch1@t, .z=ch0@t+1, .w=ch1@t+1
        const float v0x = fminf(1.f, q0.x), v0y = fminf(1.f, q0.y);
        const float v0z = fminf(1.f, q0.z), v0w = fminf(1.f, q0.w);
        const float v1x = fminf(1.f, q1.x), v1y = fminf(1.f, q1.y);
        const float v1z = fminf(1.f, q1.z), v1w = fminf(1.f, q1.w);

        // Per-thread composed op over 4 timesteps, folded back-to-front.
        float Px = p1.z, Vx = v1z;
        float Py = p1.w, Vy = v1w;
        Vx = fmaxf(v1x, fminf(p1.x, Vx)); Px = fminf(p1.x, Px);
        Vy = fmaxf(v1y, fminf(p1.y, Vy)); Py = fminf(p1.y, Py);
        Vx = fmaxf(v0z, fminf(p0.z, Vx)); Px = fminf(p0.z, Px);
        Vy = fmaxf(v0w, fminf(p0.w, Vy)); Py = fminf(p0.w, Py);
        Vx = fmaxf(v0x, fminf(p0.x, Vx)); Px = fminf(p0.x, Px);
        Vy = fmaxf(v0y, fminf(p0.y, Vy)); Py = fminf(p0.y, Py);

        // Warp-level reverse inclusive scan (suffix compositions).
#pragma unroll
        for (int off = 1; off < 32; off <<= 1) {
            float Px2 = __shfl_down_sync(0xffffffffu, Px, off);
            float Vx2 = __shfl_down_sync(0xffffffffu, Vx, off);
            float Py2 = __shfl_down_sync(0xffffffffu, Py, off);
            float Vy2 = __shfl_down_sync(0xffffffffu, Vy, off);
            if (lane + off < 32) {
                Vx = fmaxf(Vx, fminf(Px, Vx2)); Px = fminf(Px, Px2);
                Vy = fmaxf(Vy, fminf(Py, Vy2)); Py = fminf(Py, Py2);
            }
        }
        // Exclusive within warp (suffix from lane+1); lane 31 = identity.
        float EPx = __shfl_down_sync(0xffffffffu, Px, 1);
        float EVx = __shfl_down_sync(0xffffffffu, Vx, 1);
        float EPy = __shfl_down_sync(0xffffffffu, Py, 1);
        float EVy = __shfl_down_sync(0xffffffffu, Vy, 1);
        if (lane == 31) { EPx = finf(); EVx = fninf(); EPy = finf(); EVy = fninf(); }

        // B2: all threads done reading sp/sq[buf] (WAR for the reissue below)
        // and done reading wop from the previous iteration.
        __syncthreads();
        if (lane == 0) wop[w] = make_float4(Px, Vx, Py, Vy);

        // Reissue this buffer for segment i-2 (arrives 2 iterations from now).
        if (i >= 2) {
            const size_t ns = base + (size_t)(i - 2) * SEG_F4;
            cpa16(dp0[buf], phi + ns + tid);
            cpa16(dp1[buf], phi + ns + BLK + tid);
            cpa16(dq0[buf], psi + ns + tid);
            cpa16(dq1[buf], psi + ns + BLK + tid);
            asm volatile("cp.async.commit_group;" ::: "memory");
        }
        __syncthreads();   // B3: wop visible

        // Cross-warp resolve, redundant in every warp (NW=4 -> 2 steps).
        float4 o = wop[lane & (NW - 1)];
        float WPx = o.x, WVx = o.y, WPy = o.z, WVy = o.w;
#pragma unroll
        for (int off = 1; off < NW; off <<= 1) {
            float P2 = __shfl_down_sync(0xffffffffu, WPx, off);
            float V2 = __shfl_down_sync(0xffffffffu, WVx, off);
            float P3 = __shfl_down_sync(0xffffffffu, WPy, off);
            float V3 = __shfl_down_sync(0xffffffffu, WVy, off);
            if (lane + off < NW) {
                WVx = fmaxf(WVx, fminf(WPx, V2)); WPx = fminf(WPx, P2);
                WVy = fmaxf(WVy, fminf(WPy, V3)); WPy = fminf(WPy, P3);
            }
        }
        // Entering op for THIS warp = inclusive suffix at w+1 (identity for last).
        float XPx = __shfl_sync(0xffffffffu, WPx, (w + 1) & 31);
        float XVx = __shfl_sync(0xffffffffu, WVx, (w + 1) & 31);
        float XPy = __shfl_sync(0xffffffffu, WPy, (w + 1) & 31);
        float XVy = __shfl_sync(0xffffffffu, WVy, (w + 1) & 31);
        if (w == NW - 1) { XPx = finf(); XVx = fninf(); XPy = finf(); XVy = fninf(); }
        // Block aggregate = inclusive suffix at lane 0.
        float BPx = __shfl_sync(0xffffffffu, WPx, 0);
        float BVx = __shfl_sync(0xffffffffu, WVx, 0);
        float BPy = __shfl_sync(0xffffffffu, WPy, 0);
        float BVy = __shfl_sync(0xffffffffu, WVy, 0);

        // Entering value for this warp, then this thread.
        float winx = fmaxf(XVx, fminf(XPx, cx));
        float winy = fmaxf(XVy, fminf(XPy, cy));
        float rx = fmaxf(EVx, fminf(EPx, winx));
        float ry = fmaxf(EVy, fminf(EPy, winy));

        // Update carry (identical in every warp).
        cx = fmaxf(BVx, fminf(BPx, cx));
        cy = fmaxf(BVy, fminf(BPy, cy));

        // Sweep this thread's 4 timesteps; direct 32B/thread stores.
        const size_t seg = base + (size_t)i * SEG_F4;
        float4 o1, o0;
        o1.z = fmaxf(v1z, fminf(p1.z, rx));
        o1.w = fmaxf(v1w, fminf(p1.w, ry));
        o1.x = fmaxf(v1x, fminf(p1.x, o1.z));
        o1.y = fmaxf(v1y, fminf(p1.y, o1.w));
        o0.z = fmaxf(v0z, fminf(p0.z, o1.x));
        o0.w = fmaxf(v0w, fminf(p0.w, o1.y));
        o0.x = fmaxf(v0x, fminf(p0.x, o0.z));
        o0.y = fmaxf(v0y, fminf(p0.y, o0.w));

        out[seg + e0] = o0;
        out[seg + e1] = o1;
    }
}

extern "C" void kernel_launch(void* const* d_in, const int* in_sizes, int n_in,
                              void* d_out, int out_size)
{
    const float4* phi = (const float4*)d_in[0];
    const float4* psi = (const float4*)d_in[1];
    float4*       o   = (float4*)d_out;
    until_kernel<<<B_ROWS, BLK>>>(phi, psi, o);
}